// round 6
// baseline (speedup 1.0000x reference)
#include <cuda_runtime.h>
#include <cuda_fp16.h>
#include <math.h>

#define NN 50000
#define MM 1250000
#define H  64
#define NCH 782   // ceil(NN/64)

typedef unsigned long long ull;

__device__ float g_hA[NN*H];
__device__ float g_hB[NN*H];
__device__ __half2 g_hmA[NN*32];
__device__ __half2 g_hmB[NN*32];
__device__ float g_Ad[NN*H];
__device__ float g_Bd[NN*H];
__device__ int   g_src[MM];
__device__ int   g_dst[MM];
__device__ int   g_rank[MM];
__device__ int2  g_sa[MM];
__device__ int2  g_csr[MM];
__device__ int   g_cnt[NN];
__device__ int   g_rowptr[NN+1];
__device__ int   g_is64;
__device__ int   g_bsum[256];
__device__ int   g_boff[256];
// packed tables
__device__ ull g_Wih_p[64*3*32];
__device__ ull g_Whh_p[64*3*32];
__device__ ull g_W2_p[64*16];
__device__ ull g_W1e_p[5*32];
__device__ ull g_Whm_p[64*32];   // (msW[2l][k], msW[2l+1][k]) at k*32+l
__device__ ull g_Wa_p[64*32];    // (W1[2l][k], W1[2l+1][k])  at k*32+l
__device__ ull g_Wb_p[64*32];    // (W1[2l][64+k], W1[2l+1][64+k])
__device__ ull g_We_p[5*16];
__device__ float g_b1e[32];
__device__ float g_W2e[32];
__device__ float g_bhe[64];

__device__ __forceinline__ float sigf(float x){ return 1.f/(1.f+__expf(-x)); }
__device__ __forceinline__ ull ffma2(ull a, ull b, ull c){
  ull d; asm("fma.rn.f32x2 %0, %1, %2, %3;" : "=l"(d) : "l"(a), "l"(b), "l"(c)); return d;
}
__device__ __forceinline__ ull dup2(float v){
  ull r; asm("mov.b64 %0, {%1, %1};" : "=l"(r) : "f"(v)); return r;
}
__device__ __forceinline__ ull pk2(float lo, float hi){
  ull r; asm("mov.b64 %0, {%1, %2};" : "=l"(r) : "f"(lo), "f"(hi)); return r;
}
__device__ __forceinline__ void unpk2(ull p, float& lo, float& hi){
  asm("mov.b64 {%0, %1}, %2;" : "=f"(lo), "=f"(hi) : "l"(p));
}

// ---------- merged prologue: zero + detect + all weight packing ----------
__global__ void k_init(const int* __restrict__ ei,
                       const float* __restrict__ Wih, const float* __restrict__ Whh,
                       const float* __restrict__ dW2, const float* __restrict__ dW1,
                       const float* __restrict__ msW,
                       const float* __restrict__ eW1, const float* __restrict__ eb1,
                       const float* __restrict__ eW2,
                       const float* __restrict__ Win, const float* __restrict__ bin,
                       const float* __restrict__ u){
  int b = blockIdx.x, t = threadIdx.x;
  if (b < 196){
    int i = b*256 + t;
    if (i < NN) g_cnt[i] = 0;
  } else if (b == 196){
    __shared__ int nz;
    if (t == 0) nz = 0;
    __syncthreads();
    int c = 0;
    for (int i = t; i < 4096; i += 256) c += (ei[2*i+1] != 0);
    if (c) atomicAdd(&nz, 1);
    __syncthreads();
    if (t == 0) g_is64 = (nz == 0);
  } else if (b < 226){                       // packw: 7328 items
    int i = (b-197)*256 + t;
    if (i < 6144){
      int jp = i & 31, r = i >> 5, g = r % 3, k = r / 3;
      g_Wih_p[i] = pk2(Wih[(g*64+jp)*64 + k], Wih[(g*64+jp+32)*64 + k]);
      g_Whh_p[i] = pk2(Whh[(g*64+jp)*64 + k], Whh[(g*64+jp+32)*64 + k]);
    } else if (i < 7168){
      int q = i - 6144;
      int jp = q & 15, k = q >> 4;
      g_W2_p[q] = pk2(dW2[jp*64 + k], dW2[(jp+16)*64 + k]);
    } else if (i < 7328){
      int q = i - 7168;
      int jp = q & 31, k = q >> 5;
      g_W1e_p[q] = pk2(dW1[jp*133 + 128 + k], dW1[(jp+32)*133 + 128 + k]);
    }
  } else if (b < 235){                       // packw2: 2224 items
    int i = (b-226)*256 + t;
    if (i < 2048){
      int l = i & 31, k = i >> 5;
      g_Whm_p[i] = pk2(msW[(2*l)*64 + k], msW[(2*l+1)*64 + k]);
    } else if (i < 2128){
      int q = i - 2048;
      int ip = q & 15, k = q >> 4;
      g_We_p[q] = pk2(eW1[ip*16 + k], eW1[(ip+16)*16 + k]);
    } else if (i < 2160){
      int q = i - 2128;
      float acc = eb1[q];
      #pragma unroll
      for (int k = 0; k < 11; k++) acc = fmaf(u[k], eW1[q*16 + 5 + k], acc);
      g_b1e[q] = acc;
      g_W2e[q] = eW2[q];
    } else if (i < 2224){
      int j = i - 2160;
      float acc = bin[j];
      #pragma unroll
      for (int k = 0; k < 11; k++) acc = fmaf(u[k], Win[j*23 + 12 + k], acc);
      g_bhe[j] = acc;
    }
  } else {                                   // pack AB: 4096 items
    int i = (b-235)*256 + t;
    if (i < 2048){
      int l = i & 31, k = i >> 5;
      g_Wa_p[i] = pk2(dW1[(2*l)*133 + k], dW1[(2*l+1)*133 + k]);
    } else if (i < 4096){
      int q = i - 2048;
      int l = q & 31, k = q >> 5;
      g_Wb_p[q] = pk2(dW1[(2*l)*133 + 64 + k], dW1[(2*l+1)*133 + 64 + k]);
    }
  }
}

// ---------- per-edge alpha + histogram ----------
__global__ void __launch_bounds__(256) k_prep(
    const void* __restrict__ ei, const float* __restrict__ ea,
    const float* __restrict__ b2){
  __shared__ float sEA[1280];
  __shared__ ull sWe[80], sB1[16];
  __shared__ float sW2[32];
  __shared__ float sb2;
  int t = threadIdx.x;
  int base = blockIdx.x*256;
  for (int i = t; i < 80; i += 256) sWe[i] = g_We_p[i];
  if (t < 16) sB1[t] = pk2(g_b1e[t], g_b1e[t+16]);
  if (t < 32) sW2[t] = g_W2e[t];
  if (t == 0) sb2 = b2[0];
  {
    int lim = MM*5 - base*5;
    for (int i = t; i < 1280 && i < lim; i += 256) sEA[i] = ea[base*5 + i];
  }
  __syncthreads();
  int e = base + t;
  if (e >= MM) return;
  int s, d;
  if (g_is64){
    const long long* p = (const long long*)ei;
    s = (int)p[e]; d = (int)p[MM + e];
  } else {
    const int* p = (const int*)ei;
    s = p[e]; d = p[MM + e];
  }
  g_src[e] = s; g_dst[e] = d;
  g_rank[e] = atomicAdd(&g_cnt[d], 1);
  float f[5];
  #pragma unroll
  for (int k = 0; k < 5; k++) f[k] = sEA[t*5 + k];
  ull ap[16];
  #pragma unroll
  for (int i = 0; i < 16; i++) ap[i] = sB1[i];
  #pragma unroll
  for (int k = 0; k < 5; k++){
    ull fv = dup2(f[k]);
    #pragma unroll
    for (int i = 0; i < 16; i++) ap[i] = ffma2(fv, sWe[k*16 + i], ap[i]);
  }
  float acc = sb2;
  #pragma unroll
  for (int i = 0; i < 16; i++){
    float lo, hi; unpk2(ap[i], lo, hi);
    acc = fmaf(fmaxf(lo, 0.f), sW2[i], acc);
    acc = fmaf(fmaxf(hi, 0.f), sW2[i+16], acc);
  }
  g_sa[e] = make_int2(s, __float_as_int(sigf(acc)));
}

#define SCB 196
__global__ void k_scan1(){
  int b = blockIdx.x, t = threadIdx.x;
  int i = b*256 + t;
  int v = (i < NN) ? g_cnt[i] : 0;
  __shared__ int ws[8];
  int lane = t & 31, wid = t >> 5;
  #pragma unroll
  for (int o = 16; o >= 1; o >>= 1) v += __shfl_down_sync(~0u, v, o);
  if (lane == 0) ws[wid] = v;
  __syncthreads();
  if (t == 0){
    int s = 0;
    #pragma unroll
    for (int w = 0; w < 8; w++) s += ws[w];
    g_bsum[b] = s;
  }
}
__global__ void k_scan2(){
  int t = threadIdx.x;
  int v = (t < SCB) ? g_bsum[t] : 0;
  int lane = t & 31, wid = t >> 5;
  __shared__ int ws[8], wo[8];
  int x = v;
  #pragma unroll
  for (int o = 1; o < 32; o <<= 1){ int u = __shfl_up_sync(~0u, x, o); if (lane >= o) x += u; }
  if (lane == 31) ws[wid] = x;
  __syncthreads();
  if (t == 0){
    int s = 0;
    #pragma unroll
    for (int w = 0; w < 8; w++){ wo[w] = s; s += ws[w]; }
  }
  __syncthreads();
  g_boff[t] = x - v + wo[wid];
}
__global__ void k_scan3(){
  int b = blockIdx.x, t = threadIdx.x;
  int i = b*256 + t;
  int v = (i < NN) ? g_cnt[i] : 0;
  int lane = t & 31, wid = t >> 5;
  __shared__ int ws[8], wo[8];
  int x = v;
  #pragma unroll
  for (int o = 1; o < 32; o <<= 1){ int u = __shfl_up_sync(~0u, x, o); if (lane >= o) x += u; }
  if (lane == 31) ws[wid] = x;
  __syncthreads();
  if (t == 0){
    int s = 0;
    #pragma unroll
    for (int w = 0; w < 8; w++){ wo[w] = s; s += ws[w]; }
  }
  __syncthreads();
  int excl = x - v + wo[wid] + g_boff[b];
  if (i < NN) g_rowptr[i+1] = excl + v;
  if (i == 0) g_rowptr[0] = 0;
}

__global__ void k_fill(){
  int e = blockIdx.x*blockDim.x + threadIdx.x;
  if (e >= MM) return;
  int d = g_dst[e];
  g_csr[g_rowptr[d] + g_rank[e]] = g_sa[e];
}

// ---------- input projection (bias pre-folded with u) ----------
__global__ void k_h2(const float* __restrict__ x, const float* __restrict__ Win){
  __shared__ float sW[64*12], sb[64];
  int t = threadIdx.x;
  for (int i = t; i < 64*12; i += blockDim.x){ int j = i/12, k = i%12; sW[i] = Win[j*23 + k]; }
  if (t < 64) sb[t] = g_bhe[t];
  __syncthreads();
  int idx = blockIdx.x*blockDim.x + t;
  if (idx >= NN*H) return;
  int node = idx >> 6, j = idx & 63;
  const float* w = &sW[j*12];
  const float* xr = &x[node*12];
  float acc = sb[j];
  #pragma unroll
  for (int k = 0; k < 12; k++) acc = fmaf(xr[k], w[k], acc);
  g_hA[idx] = tanhf(acc);
}

// ---------- initial hm (standalone) ----------
__global__ void k_hm0(const float* __restrict__ hin, __half2* __restrict__ hmout,
                      const float* __restrict__ b){
  __shared__ ull sW[64*32];
  __shared__ ull sbp[32];
  int t = threadIdx.x;
  for (int i = t; i < 2048; i += blockDim.x) sW[i] = g_Whm_p[i];
  if (t < 32) sbp[t] = pk2(b[2*t], b[2*t+1]);
  __syncthreads();
  int lane = t & 31;
  int wg = (blockIdx.x*blockDim.x + t) >> 5;
  int nw = (gridDim.x*blockDim.x) >> 5;
  for (int n = wg; n < NN; n += nw){
    float v0 = hin[(n<<6) + lane], v1 = hin[(n<<6) + 32 + lane];
    ull ap = sbp[lane];
    #pragma unroll 8
    for (int k = 0; k < 32; k++)
      ap = ffma2(dup2(__shfl_sync(~0u, v0, k)), sW[k*32 + lane], ap);
    #pragma unroll 8
    for (int k = 0; k < 32; k++)
      ap = ffma2(dup2(__shfl_sync(~0u, v1, k)), sW[(32+k)*32 + lane], ap);
    float lo, hi; unpk2(ap, lo, hi);
    hmout[n*32 + lane] = __floats2half2_rn(fmaxf(lo, 0.f), fmaxf(hi, 0.f));
  }
}

// ---------- fused step: agg -> GRU -> (hm | AB) ----------
#define STEP_SMEM (18432*8 + 64*64*4)
__global__ void __launch_bounds__(512,1) k_step(
    const float* __restrict__ hin, float* __restrict__ hout,
    const __half2* __restrict__ hmin, __half2* __restrict__ hmout,
    const float* __restrict__ bih, const float* __restrict__ bhh,
    const float* __restrict__ msb, const float* __restrict__ db1,
    int last){
  extern __shared__ ull sw[];
  ull* sWi = sw;                // 6144
  ull* sWh = sw + 6144;         // 6144
  ull* sHm = sw + 12288;        // 2048
  ull* sWa = sw + 14336;        // 2048
  ull* sWb = sw + 16384;        // 2048
  float* sAgg = (float*)(sw + 18432);  // 64 nodes x 64 f
  __shared__ float sbi[192], sbh[192];
  __shared__ ull sMb[32], sB1[32];
  int t = threadIdx.x;
  for (int i = t; i < 6144; i += 512){ sWi[i] = g_Wih_p[i]; sWh[i] = g_Whh_p[i]; }
  if (!last){
    for (int i = t; i < 2048; i += 512) sHm[i] = g_Whm_p[i];
  } else {
    for (int i = t; i < 2048; i += 512){ sWa[i] = g_Wa_p[i]; sWb[i] = g_Wb_p[i]; }
  }
  if (t < 192){ sbi[t] = bih[t]; sbh[t] = bhh[t]; }
  if (t < 32){ sMb[t] = pk2(msb[2*t], msb[2*t+1]); sB1[t] = pk2(db1[2*t], db1[2*t+1]); }
  __syncthreads();
  int w = t >> 5, lane = t & 31;
  for (int c = blockIdx.x; c < NCH; c += gridDim.x){
    int nb = c*64 + w*4;
    // ---- agg phase (warp per node, 4 nodes per warp) ----
    #pragma unroll
    for (int ii = 0; ii < 4; ii++){
      int n = nb + ii;
      float ax = 0.f, ay = 0.f, inv = 0.f;
      if (n < NN){
        int beg = g_rowptr[n], end = g_rowptr[n+1];
        int i = beg;
        for (; i + 1 < end; i += 2){
          int2 e0 = g_csr[i], e1 = g_csr[i+1];
          float al0 = __int_as_float(e0.y), al1 = __int_as_float(e1.y);
          float2 f0 = __half22float2(hmin[(size_t)e0.x*32 + lane]);
          float2 f1 = __half22float2(hmin[(size_t)e1.x*32 + lane]);
          ax = fmaf(al0, f0.x, ax); ay = fmaf(al0, f0.y, ay);
          ax = fmaf(al1, f1.x, ax); ay = fmaf(al1, f1.y, ay);
        }
        if (i < end){
          int2 e0 = g_csr[i];
          float al0 = __int_as_float(e0.y);
          float2 f0 = __half22float2(hmin[(size_t)e0.x*32 + lane]);
          ax = fmaf(al0, f0.x, ax); ay = fmaf(al0, f0.y, ay);
        }
        inv = 1.f / fmaxf((float)(end - beg), 1.f);
      }
      ((float2*)sAgg)[(w*4+ii)*32 + lane] = make_float2(ax*inv, ay*inv);
    }
    __syncthreads();
    // ---- GRU phase (same 4 nodes per warp) ----
    float ra0[4], ra1[4], rh0[4], rh1[4];
    #pragma unroll
    for (int i = 0; i < 4; i++){
      int n = min(nb + i, NN - 1);
      ra0[i] = sAgg[(w*4+i)*64 + lane];
      ra1[i] = sAgg[(w*4+i)*64 + 32 + lane];
      rh0[i] = hin[(n<<6) + lane];
      rh1[i] = hin[(n<<6) + 32 + lane];
    }
    ull R[4], Z[4], Ng[4], Rh[4], Zh[4], Nh[4];
    #pragma unroll
    for (int i = 0; i < 4; i++){ R[i]=Z[i]=Ng[i]=Rh[i]=Zh[i]=Nh[i]=0ull; }
    #pragma unroll 4
    for (int k = 0; k < 32; k++){
      ull wir = sWi[(k*3+0)*32 + lane], wiz = sWi[(k*3+1)*32 + lane], win = sWi[(k*3+2)*32 + lane];
      ull whr = sWh[(k*3+0)*32 + lane], whz = sWh[(k*3+1)*32 + lane], whn = sWh[(k*3+2)*32 + lane];
      #pragma unroll
      for (int i = 0; i < 4; i++){
        ull av = dup2(__shfl_sync(~0u, ra0[i], k));
        ull hv = dup2(__shfl_sync(~0u, rh0[i], k));
        R[i]  = ffma2(av, wir, R[i]);  Z[i]  = ffma2(av, wiz, Z[i]);  Ng[i] = ffma2(av, win, Ng[i]);
        Rh[i] = ffma2(hv, whr, Rh[i]); Zh[i] = ffma2(hv, whz, Zh[i]); Nh[i] = ffma2(hv, whn, Nh[i]);
      }
    }
    #pragma unroll 4
    for (int k = 32; k < 64; k++){
      ull wir = sWi[(k*3+0)*32 + lane], wiz = sWi[(k*3+1)*32 + lane], win = sWi[(k*3+2)*32 + lane];
      ull whr = sWh[(k*3+0)*32 + lane], whz = sWh[(k*3+1)*32 + lane], whn = sWh[(k*3+2)*32 + lane];
      #pragma unroll
      for (int i = 0; i < 4; i++){
        ull av = dup2(__shfl_sync(~0u, ra1[i], k - 32));
        ull hv = dup2(__shfl_sync(~0u, rh1[i], k - 32));
        R[i]  = ffma2(av, wir, R[i]);  Z[i]  = ffma2(av, wiz, Z[i]);  Ng[i] = ffma2(av, win, Ng[i]);
        Rh[i] = ffma2(hv, whr, Rh[i]); Zh[i] = ffma2(hv, whz, Zh[i]); Nh[i] = ffma2(hv, whn, Nh[i]);
      }
    }
    float birL = sbi[lane],     birH = sbi[lane+32];
    float bizL = sbi[64+lane],  bizH = sbi[96+lane];
    float binL = sbi[128+lane], binH = sbi[160+lane];
    float bhrL = sbh[lane],     bhrH = sbh[lane+32];
    float bhzL = sbh[64+lane],  bhzH = sbh[96+lane];
    float bhnL = sbh[128+lane], bhnH = sbh[160+lane];
    #pragma unroll
    for (int i = 0; i < 4; i++){
      int n = nb + i;
      bool ok = (n < NN);
      float rL,rH,zL,zH,ngL,ngH, aL,aH,bL,bH;
      unpk2(R[i],  aL, aH); unpk2(Rh[i], bL, bH);
      rL = sigf(aL + birL + bL + bhrL); rH = sigf(aH + birH + bH + bhrH);
      unpk2(Z[i],  aL, aH); unpk2(Zh[i], bL, bH);
      zL = sigf(aL + bizL + bL + bhzL); zH = sigf(aH + bizH + bH + bhzH);
      unpk2(Ng[i], aL, aH); unpk2(Nh[i], bL, bH);
      ngL = tanhf(aL + binL + rL*(bL + bhnL));
      ngH = tanhf(aH + binH + rH*(bH + bhnH));
      float hnL = (1.f - zL)*ngL + zL*rh0[i];
      float hnH = (1.f - zH)*ngH + zH*rh1[i];
      if (ok){
        hout[(n<<6) + lane]      = hnL;
        hout[(n<<6) + 32 + lane] = hnH;
      }
      if (!last){
        ull ap = sMb[lane];
        #pragma unroll 8
        for (int k = 0; k < 32; k++)
          ap = ffma2(dup2(__shfl_sync(~0u, hnL, k)), sHm[k*32 + lane], ap);
        #pragma unroll 8
        for (int k = 0; k < 32; k++)
          ap = ffma2(dup2(__shfl_sync(~0u, hnH, k)), sHm[(32+k)*32 + lane], ap);
        float lo, hi; unpk2(ap, lo, hi);
        if (ok) hmout[n*32 + lane] = __floats2half2_rn(fmaxf(lo, 0.f), fmaxf(hi, 0.f));
      } else {
        ull aA = sB1[lane], aB = 0ull;
        #pragma unroll 8
        for (int k = 0; k < 32; k++){
          ull v = dup2(__shfl_sync(~0u, hnL, k));
          aA = ffma2(v, sWa[k*32 + lane], aA);
          aB = ffma2(v, sWb[k*32 + lane], aB);
        }
        #pragma unroll 8
        for (int k = 0; k < 32; k++){
          ull v = dup2(__shfl_sync(~0u, hnH, k));
          aA = ffma2(v, sWa[(32+k)*32 + lane], aA);
          aB = ffma2(v, sWb[(32+k)*32 + lane], aB);
        }
        float alo, ahi, blo, bhi;
        unpk2(aA, alo, ahi); unpk2(aB, blo, bhi);
        if (ok){
          ((float2*)g_Ad)[n*32 + lane] = make_float2(alo, ahi);
          ((float2*)g_Bd)[n*32 + lane] = make_float2(blo, bhi);
        }
      }
    }
    __syncthreads();
  }
}

// ---------- decoder ----------
__global__ void __launch_bounds__(256) k_dec(
    const float* __restrict__ ea, float* __restrict__ out,
    const float* __restrict__ b2, const float* __restrict__ W3,
    const float* __restrict__ b3){
  __shared__ __align__(16) ull sW1[160];
  __shared__ __align__(16) ull sW2[1024];
  __shared__ float4 sW3[32];
  __shared__ float sb2[32], sb3[4];
  __shared__ float sEA[1280];
  int t = threadIdx.x;
  int base = blockIdx.x*256;
  for (int i = t; i < 160;  i += blockDim.x) sW1[i] = g_W1e_p[i];
  for (int i = t; i < 1024; i += blockDim.x) sW2[i] = g_W2_p[i];
  {
    float* p3 = (float*)sW3;
    for (int i = t; i < 128; i += blockDim.x) p3[i] = W3[i];
  }
  if (t < 32) sb2[t] = b2[t];
  if (t < 4)  sb3[t] = b3[t];
  {
    int lim = MM*5 - base*5;
    for (int i = t; i < 1280 && i < lim; i += 256) sEA[i] = ea[base*5 + i];
  }
  __syncthreads();
  int e = base + t;
  if (e >= MM) return;
  int s = g_src[e], d = g_dst[e];
  const float4* pA = (const float4*)&g_Ad[(size_t)s << 6];
  const float4* pB = (const float4*)&g_Bd[(size_t)d << 6];
  ull s1p[32];
  #pragma unroll
  for (int q = 0; q < 8; q++){
    float4 aL = __ldg(&pA[q]),   bL = __ldg(&pB[q]);
    float4 aH = __ldg(&pA[q+8]), bH = __ldg(&pB[q+8]);
    s1p[4*q]   = pk2(aL.x + bL.x, aH.x + bH.x);
    s1p[4*q+1] = pk2(aL.y + bL.y, aH.y + bH.y);
    s1p[4*q+2] = pk2(aL.z + bL.z, aH.z + bH.z);
    s1p[4*q+3] = pk2(aL.w + bL.w, aH.w + bH.w);
  }
  const ulonglong2* w1 = (const ulonglong2*)sW1;
  #pragma unroll
  for (int k = 0; k < 5; k++){
    ull ev = dup2(sEA[t*5 + k]);
    #pragma unroll
    for (int q = 0; q < 16; q++){
      ulonglong2 wq = w1[k*16 + q];
      s1p[2*q]   = ffma2(ev, wq.x, s1p[2*q]);
      s1p[2*q+1] = ffma2(ev, wq.y, s1p[2*q+1]);
    }
  }
  float s1[64];
  #pragma unroll
  for (int jp = 0; jp < 32; jp++){
    float lo, hi; unpk2(s1p[jp], lo, hi);
    s1[jp] = fmaxf(lo, 0.f); s1[jp+32] = fmaxf(hi, 0.f);
  }
  ull a2p[16];
  #pragma unroll
  for (int jp = 0; jp < 16; jp++) a2p[jp] = pk2(sb2[jp], sb2[jp+16]);
  const ulonglong2* w2 = (const ulonglong2*)sW2;
  #pragma unroll 8
  for (int k = 0; k < 64; k++){
    ull sd = dup2(s1[k]);
    #pragma unroll
    for (int q = 0; q < 8; q++){
      ulonglong2 wq = w2[k*8 + q];
      a2p[2*q]   = ffma2(sd, wq.x, a2p[2*q]);
      a2p[2*q+1] = ffma2(sd, wq.y, a2p[2*q+1]);
    }
  }
  float a2[32];
  #pragma unroll
  for (int jp = 0; jp < 16; jp++){
    float lo, hi; unpk2(a2p[jp], lo, hi);
    a2[jp] = fmaxf(lo, 0.f); a2[jp+16] = fmaxf(hi, 0.f);
  }
  float o[4];
  #pragma unroll
  for (int j = 0; j < 4; j++){
    float acc = sb3[j];
    #pragma unroll
    for (int q = 0; q < 8; q++){
      float4 wv = sW3[j*8 + q];
      acc = fmaf(a2[4*q],   wv.x, acc);
      acc = fmaf(a2[4*q+1], wv.y, acc);
      acc = fmaf(a2[4*q+2], wv.z, acc);
      acc = fmaf(a2[4*q+3], wv.w, acc);
    }
    o[j] = acc;
  }
  ((float4*)out)[e] = make_float4(o[0], o[1], o[2], o[3]);
}

extern "C" void kernel_launch(void* const* d_in, const int* in_sizes, int n_in,
                              void* d_out, int out_size){
  (void)in_sizes; (void)n_in; (void)out_size;
  const float* x    = (const float*)d_in[0];
  const void*  ei   = d_in[1];
  const float* ea   = (const float*)d_in[2];
  const float* u    = (const float*)d_in[3];
  const float* Win  = (const float*)d_in[4];
  const float* bin  = (const float*)d_in[5];
  const float* eW1  = (const float*)d_in[6];
  const float* eb1  = (const float*)d_in[7];
  const float* eW2  = (const float*)d_in[8];
  const float* eb2  = (const float*)d_in[9];
  const float* msW  = (const float*)d_in[10];
  const float* msb  = (const float*)d_in[11];
  const float* Wih  = (const float*)d_in[12];
  const float* bih  = (const float*)d_in[13];
  const float* Whh  = (const float*)d_in[14];
  const float* bhh  = (const float*)d_in[15];
  const float* dW1  = (const float*)d_in[16];
  const float* db1  = (const float*)d_in[17];
  const float* dW2  = (const float*)d_in[18];
  const float* db2  = (const float*)d_in[19];
  const float* dW3  = (const float*)d_in[20];
  const float* db3  = (const float*)d_in[21];
  float* out = (float*)d_out;

  static int init_done = 0;
  static cudaStream_t s1;
  static cudaEvent_t evA, evB;
  if (!init_done){
    cudaFuncSetAttribute(k_step, cudaFuncAttributeMaxDynamicSharedMemorySize, STEP_SMEM);
    cudaStreamCreateWithFlags(&s1, cudaStreamNonBlocking);
    cudaEventCreateWithFlags(&evA, cudaEventDisableTiming);
    cudaEventCreateWithFlags(&evB, cudaEventDisableTiming);
    init_done = 1;
  }

  float *hA_p = nullptr, *hB_p = nullptr;
  __half2 *hmA_p = nullptr, *hmB_p = nullptr;
  cudaGetSymbolAddress((void**)&hA_p, g_hA);
  cudaGetSymbolAddress((void**)&hB_p, g_hB);
  cudaGetSymbolAddress((void**)&hmA_p, g_hmA);
  cudaGetSymbolAddress((void**)&hmB_p, g_hmB);

  // merged prologue
  k_init<<<251, 256>>>((const int*)ei, Wih, Whh, dW2, dW1, msW, eW1, eb1, eW2, Win, bin, u);

  cudaEventRecord(evA, 0);
  cudaStreamWaitEvent(s1, evA, 0);

  // node chain on s1
  k_h2<<<(NN*H + 255)/256, 256, 0, s1>>>(x, Win);
  k_hm0<<<1184, 256, 0, s1>>>(hA_p, hmA_p, msb);
  cudaEventRecord(evB, s1);

  // edge chain on default stream
  k_prep<<<(MM + 255)/256, 256>>>(ei, ea, eb2);
  k_scan1<<<SCB, 256>>>();
  k_scan2<<<1, 256>>>();
  k_scan3<<<SCB, 256>>>();
  k_fill<<<(MM + 255)/256, 256>>>();

  cudaStreamWaitEvent(0, evB, 0);

  // fused steps
  k_step<<<148, 512, STEP_SMEM>>>(hA_p, hB_p, hmA_p, hmB_p, bih, bhh, msb, db1, 0);
  k_step<<<148, 512, STEP_SMEM>>>(hB_p, hA_p, hmB_p, hmA_p, bih, bhh, msb, db1, 0);
  k_step<<<148, 512, STEP_SMEM>>>(hA_p, hB_p, hmA_p, hmB_p, bih, bhh, msb, db1, 1);

  k_dec<<<(MM + 255)/256, 256>>>(ea, out, db2, dW3, db3);
}

// round 9
// speedup vs baseline: 1.0718x; 1.0718x over previous
#include <cuda_runtime.h>
#include <cuda_fp16.h>
#include <math.h>

#define NN 50000
#define MM 1250000
#define H  64

typedef unsigned long long ull;

__device__ float g_hA[NN*H];
__device__ float g_hB[NN*H];
__device__ float g_agg[NN*H];
__device__ __half2 g_hmA[NN*32];
__device__ __half2 g_hmB[NN*32];
__device__ float g_Ad[NN*H];
__device__ float g_Bd[NN*H];
__device__ int2  g_sd[MM];       // (src,dst) for decoder
__device__ int2  g_csr[MM];      // (src, alpha-bits) bucketed by dst
__device__ int   g_cnt[NN];
__device__ int   g_rowptr[NN+1];
__device__ int   g_cursor[NN];
__device__ int   g_is64;
__device__ int   g_bsum[256];
__device__ int   g_boff[256];
// packed tables
__device__ ull g_Wih_p[64*3*32];
__device__ ull g_Whh_p[64*3*32];
__device__ ull g_W2_p[64*16];
__device__ ull g_W1e_p[5*32];
__device__ ull g_Whm_p[64*32];
__device__ ull g_We_p[5*16];
__device__ float g_b1e[32];
__device__ float g_W2e[32];
__device__ float g_bhe[64];

__device__ __forceinline__ float sigf(float x){ return 1.f/(1.f+__expf(-x)); }
__device__ __forceinline__ ull ffma2(ull a, ull b, ull c){
  ull d; asm("fma.rn.f32x2 %0, %1, %2, %3;" : "=l"(d) : "l"(a), "l"(b), "l"(c)); return d;
}
__device__ __forceinline__ ull dup2(float v){
  ull r; asm("mov.b64 %0, {%1, %1};" : "=l"(r) : "f"(v)); return r;
}
__device__ __forceinline__ ull pk2(float lo, float hi){
  ull r; asm("mov.b64 %0, {%1, %2};" : "=l"(r) : "f"(lo), "f"(hi)); return r;
}
__device__ __forceinline__ void unpk2(ull p, float& lo, float& hi){
  asm("mov.b64 {%0, %1}, %2;" : "=f"(lo), "=f"(hi) : "l"(p));
}

// ---------- merged prologue: zero + detect + all packing ----------
__global__ void k_init(const int* __restrict__ ei,
                       const float* __restrict__ Wih, const float* __restrict__ Whh,
                       const float* __restrict__ dW2, const float* __restrict__ dW1,
                       const float* __restrict__ msW,
                       const float* __restrict__ eW1, const float* __restrict__ eb1,
                       const float* __restrict__ eW2,
                       const float* __restrict__ Win, const float* __restrict__ bin,
                       const float* __restrict__ u){
  int b = blockIdx.x, t = threadIdx.x;
  if (b < 196){
    int i = b*256 + t;
    if (i < NN) g_cnt[i] = 0;
  } else if (b == 196){
    __shared__ int nz;
    if (t == 0) nz = 0;
    __syncthreads();
    int c = 0;
    for (int i = t; i < 4096; i += 256) c += (ei[2*i+1] != 0);
    if (c) atomicAdd(&nz, 1);
    __syncthreads();
    if (t == 0) g_is64 = (nz == 0);
  } else if (b < 226){
    int i = (b-197)*256 + t;
    if (i < 6144){
      int jp = i & 31, r = i >> 5, g = r % 3, k = r / 3;
      g_Wih_p[i] = pk2(Wih[(g*64+jp)*64 + k], Wih[(g*64+jp+32)*64 + k]);
      g_Whh_p[i] = pk2(Whh[(g*64+jp)*64 + k], Whh[(g*64+jp+32)*64 + k]);
    } else if (i < 7168){
      int q = i - 6144;
      int jp = q & 15, k = q >> 4;
      g_W2_p[q] = pk2(dW2[jp*64 + k], dW2[(jp+16)*64 + k]);
    } else if (i < 7328){
      int q = i - 7168;
      int jp = q & 31, k = q >> 5;
      g_W1e_p[q] = pk2(dW1[jp*133 + 128 + k], dW1[(jp+32)*133 + 128 + k]);
    }
  } else {
    int i = (b-226)*256 + t;
    if (i < 2048){
      int l = i & 31, k = i >> 5;
      g_Whm_p[i] = pk2(msW[(2*l)*64 + k], msW[(2*l+1)*64 + k]);
    } else if (i < 2128){
      int q = i - 2048;
      int ip = q & 15, k = q >> 4;
      g_We_p[q] = pk2(eW1[ip*16 + k], eW1[(ip+16)*16 + k]);
    } else if (i < 2160){
      int q = i - 2128;
      float acc = eb1[q];
      #pragma unroll
      for (int k = 0; k < 11; k++) acc = fmaf(u[k], eW1[q*16 + 5 + k], acc);
      g_b1e[q] = acc;
      g_W2e[q] = eW2[q];
    } else if (i < 2224){
      int j = i - 2160;
      float acc = bin[j];
      #pragma unroll
      for (int k = 0; k < 11; k++) acc = fmaf(u[k], Win[j*23 + 12 + k], acc);
      g_bhe[j] = acc;
    }
  }
}

// ---------- pass 1: histogram of dst ----------
__global__ void __launch_bounds__(256) k_count(const void* __restrict__ ei){
  int e = blockIdx.x*blockDim.x + threadIdx.x;
  if (e >= MM) return;
  int d;
  if (g_is64) d = (int)((const long long*)ei)[MM + e];
  else        d = ((const int*)ei)[MM + e];
  atomicAdd(&g_cnt[d], 1);
}

#define SCB 196
__global__ void k_scan1(){
  int b = blockIdx.x, t = threadIdx.x;
  int i = b*256 + t;
  int v = (i < NN) ? g_cnt[i] : 0;
  __shared__ int ws[8];
  int lane = t & 31, wid = t >> 5;
  #pragma unroll
  for (int o = 16; o >= 1; o >>= 1) v += __shfl_down_sync(~0u, v, o);
  if (lane == 0) ws[wid] = v;
  __syncthreads();
  if (t == 0){
    int s = 0;
    #pragma unroll
    for (int w = 0; w < 8; w++) s += ws[w];
    g_bsum[b] = s;
  }
}
__global__ void k_scan2(){
  int t = threadIdx.x;
  int v = (t < SCB) ? g_bsum[t] : 0;
  int lane = t & 31, wid = t >> 5;
  __shared__ int ws[8], wo[8];
  int x = v;
  #pragma unroll
  for (int o = 1; o < 32; o <<= 1){ int u = __shfl_up_sync(~0u, x, o); if (lane >= o) x += u; }
  if (lane == 31) ws[wid] = x;
  __syncthreads();
  if (t == 0){
    int s = 0;
    #pragma unroll
    for (int w = 0; w < 8; w++){ wo[w] = s; s += ws[w]; }
  }
  __syncthreads();
  g_boff[t] = x - v + wo[wid];
}
__global__ void k_scan3(){
  int b = blockIdx.x, t = threadIdx.x;
  int i = b*256 + t;
  int v = (i < NN) ? g_cnt[i] : 0;
  int lane = t & 31, wid = t >> 5;
  __shared__ int ws[8], wo[8];
  int x = v;
  #pragma unroll
  for (int o = 1; o < 32; o <<= 1){ int u = __shfl_up_sync(~0u, x, o); if (lane >= o) x += u; }
  if (lane == 31) ws[wid] = x;
  __syncthreads();
  if (t == 0){
    int s = 0;
    #pragma unroll
    for (int w = 0; w < 8; w++){ wo[w] = s; s += ws[w]; }
  }
  __syncthreads();
  int excl = x - v + wo[wid] + g_boff[b];
  if (i < NN){ g_cursor[i] = excl; g_rowptr[i+1] = excl + v; }
  if (i == 0) g_rowptr[0] = 0;
}

// ---------- pass 2: alpha + direct CSR write (no separate fill) ----------
__global__ void __launch_bounds__(256) k_prep2(
    const void* __restrict__ ei, const float* __restrict__ ea,
    const float* __restrict__ b2){
  __shared__ float sEA[1280];
  __shared__ ull sWe[80], sB1[16];
  __shared__ float sW2[32];
  __shared__ float sb2;
  int t = threadIdx.x;
  int base = blockIdx.x*256;
  for (int i = t; i < 80; i += 256) sWe[i] = g_We_p[i];
  if (t < 16) sB1[t] = pk2(g_b1e[t], g_b1e[t+16]);
  if (t < 32) sW2[t] = g_W2e[t];
  if (t == 0) sb2 = b2[0];
  {
    int lim = MM*5 - base*5;
    for (int i = t; i < 1280 && i < lim; i += 256) sEA[i] = ea[base*5 + i];
  }
  __syncthreads();
  int e = base + t;
  if (e >= MM) return;
  int s, d;
  if (g_is64){
    const long long* p = (const long long*)ei;
    s = (int)p[e]; d = (int)p[MM + e];
  } else {
    const int* p = (const int*)ei;
    s = p[e]; d = p[MM + e];
  }
  g_sd[e] = make_int2(s, d);
  float f[5];
  #pragma unroll
  for (int k = 0; k < 5; k++) f[k] = sEA[t*5 + k];
  ull ap[16];
  #pragma unroll
  for (int i = 0; i < 16; i++) ap[i] = sB1[i];
  #pragma unroll
  for (int k = 0; k < 5; k++){
    ull fv = dup2(f[k]);
    #pragma unroll
    for (int i = 0; i < 16; i++) ap[i] = ffma2(fv, sWe[k*16 + i], ap[i]);
  }
  float acc = sb2;
  #pragma unroll
  for (int i = 0; i < 16; i++){
    float lo, hi; unpk2(ap[i], lo, hi);
    acc = fmaf(fmaxf(lo, 0.f), sW2[i], acc);
    acc = fmaf(fmaxf(hi, 0.f), sW2[i+16], acc);
  }
  int p = atomicAdd(&g_cursor[d], 1);
  g_csr[p] = make_int2(s, __float_as_int(sigf(acc)));
}

// ---------- input projection ----------
__global__ void k_h2(const float* __restrict__ x, const float* __restrict__ Win){
  __shared__ float sW[64*12], sb[64];
  int t = threadIdx.x;
  for (int i = t; i < 64*12; i += blockDim.x){ int j = i/12, k = i%12; sW[i] = Win[j*23 + k]; }
  if (t < 64) sb[t] = g_bhe[t];
  __syncthreads();
  int idx = blockIdx.x*blockDim.x + t;
  if (idx >= NN*H) return;
  int node = idx >> 6, j = idx & 63;
  const float* w = &sW[j*12];
  const float* xr = &x[node*12];
  float acc = sb[j];
  #pragma unroll
  for (int k = 0; k < 12; k++) acc = fmaf(xr[k], w[k], acc);
  g_hA[idx] = tanhf(acc);
}

// ---------- hm = relu(h@W.T+b) -> half2 ----------
__global__ void k_hm(const float* __restrict__ hin, __half2* __restrict__ hmout,
                     const float* __restrict__ b){
  __shared__ ull sW[64*32];
  __shared__ ull sbp[32];
  int t = threadIdx.x;
  for (int i = t; i < 2048; i += blockDim.x) sW[i] = g_Whm_p[i];
  if (t < 32) sbp[t] = pk2(b[2*t], b[2*t+1]);
  __syncthreads();
  int lane = t & 31;
  int wg = (blockIdx.x*blockDim.x + t) >> 5;
  int nw = (gridDim.x*blockDim.x) >> 5;
  for (int n = wg; n < NN; n += nw){
    float v0 = hin[(n<<6) + lane], v1 = hin[(n<<6) + 32 + lane];
    ull ap = sbp[lane];
    #pragma unroll 8
    for (int k = 0; k < 32; k++)
      ap = ffma2(dup2(__shfl_sync(~0u, v0, k)), sW[k*32 + lane], ap);
    #pragma unroll 8
    for (int k = 0; k < 32; k++)
      ap = ffma2(dup2(__shfl_sync(~0u, v1, k)), sW[(32+k)*32 + lane], ap);
    float lo, hi; unpk2(ap, lo, hi);
    hmout[n*32 + lane] = __floats2half2_rn(fmaxf(lo, 0.f), fmaxf(hi, 0.f));
  }
}

// ---------- aggregation (warp/node, 4-edge unroll) ----------
__global__ void k_agg(const __half2* __restrict__ hmin){
  int w = (blockIdx.x*blockDim.x + threadIdx.x) >> 5;
  int lane = threadIdx.x & 31;
  if (w >= NN) return;
  int beg = g_rowptr[w], end = g_rowptr[w+1];
  float ax = 0.f, ay = 0.f;
  int i = beg;
  for (; i + 3 < end; i += 4){
    int2 e0 = g_csr[i], e1 = g_csr[i+1], e2 = g_csr[i+2], e3 = g_csr[i+3];
    float2 f0 = __half22float2(hmin[(size_t)e0.x*32 + lane]);
    float2 f1 = __half22float2(hmin[(size_t)e1.x*32 + lane]);
    float2 f2 = __half22float2(hmin[(size_t)e2.x*32 + lane]);
    float2 f3 = __half22float2(hmin[(size_t)e3.x*32 + lane]);
    float a0 = __int_as_float(e0.y), a1 = __int_as_float(e1.y);
    float a2 = __int_as_float(e2.y), a3 = __int_as_float(e3.y);
    ax = fmaf(a0, f0.x, ax); ay = fmaf(a0, f0.y, ay);
    ax = fmaf(a1, f1.x, ax); ay = fmaf(a1, f1.y, ay);
    ax = fmaf(a2, f2.x, ax); ay = fmaf(a2, f2.y, ay);
    ax = fmaf(a3, f3.x, ax); ay = fmaf(a3, f3.y, ay);
  }
  for (; i < end; i++){
    int2 e0 = g_csr[i];
    float a0 = __int_as_float(e0.y);
    float2 f0 = __half22float2(hmin[(size_t)e0.x*32 + lane]);
    ax = fmaf(a0, f0.x, ax); ay = fmaf(a0, f0.y, ay);
  }
  float inv = 1.f / fmaxf((float)(end - beg), 1.f);
  ((float2*)g_agg)[w*32 + lane] = make_float2(ax*inv, ay*inv);
}

// ---------- GRU (persistent, f32x2) ----------
#define GNB 4
#define GRU_SMEM (2*6144*8)
__global__ void __launch_bounds__(256,2) k_gru(
    const float* __restrict__ hin, float* __restrict__ hout,
    const float* __restrict__ bih, const float* __restrict__ bhh){
  extern __shared__ ull sw[];
  ull* sWi = sw;
  ull* sWh = sw + 6144;
  __shared__ float sbi[192], sbh[192];
  int t = threadIdx.x;
  for (int i = t; i < 6144; i += 256){ sWi[i] = g_Wih_p[i]; sWh[i] = g_Whh_p[i]; }
  for (int i = t; i < 192; i += 256){ sbi[i] = bih[i]; sbh[i] = bhh[i]; }
  __syncthreads();
  int w = t >> 5, lane = t & 31;
  int nchunk = (NN + 31) / 32;
  for (int c = blockIdx.x; c < nchunk; c += gridDim.x){
    int nbase = c*32 + w*GNB;
    float ra0[GNB], ra1[GNB], rh0[GNB], rh1[GNB];
    #pragma unroll
    for (int i = 0; i < GNB; i++){
      int n = min(nbase + i, NN - 1);
      ra0[i] = g_agg[(n<<6) + lane];  ra1[i] = g_agg[(n<<6) + 32 + lane];
      rh0[i] = hin[(n<<6) + lane];    rh1[i] = hin[(n<<6) + 32 + lane];
    }
    ull R[GNB], Z[GNB], Ng[GNB], Rh[GNB], Zh[GNB], Nh[GNB];
    #pragma unroll
    for (int i = 0; i < GNB; i++){ R[i]=Z[i]=Ng[i]=Rh[i]=Zh[i]=Nh[i]=0ull; }
    #pragma unroll 4
    for (int k = 0; k < 32; k++){
      ull wir = sWi[(k*3+0)*32 + lane], wiz = sWi[(k*3+1)*32 + lane], win = sWi[(k*3+2)*32 + lane];
      ull whr = sWh[(k*3+0)*32 + lane], whz = sWh[(k*3+1)*32 + lane], whn = sWh[(k*3+2)*32 + lane];
      #pragma unroll
      for (int i = 0; i < GNB; i++){
        ull av = dup2(__shfl_sync(~0u, ra0[i], k));
        ull hv = dup2(__shfl_sync(~0u, rh0[i], k));
        R[i]  = ffma2(av, wir, R[i]);  Z[i]  = ffma2(av, wiz, Z[i]);  Ng[i] = ffma2(av, win, Ng[i]);
        Rh[i] = ffma2(hv, whr, Rh[i]); Zh[i] = ffma2(hv, whz, Zh[i]); Nh[i] = ffma2(hv, whn, Nh[i]);
      }
    }
    #pragma unroll 4
    for (int k = 32; k < 64; k++){
      ull wir = sWi[(k*3+0)*32 + lane], wiz = sWi[(k*3+1)*32 + lane], win = sWi[(k*3+2)*32 + lane];
      ull whr = sWh[(k*3+0)*32 + lane], whz = sWh[(k*3+1)*32 + lane], whn = sWh[(k*3+2)*32 + lane];
      #pragma unroll
      for (int i = 0; i < GNB; i++){
        ull av = dup2(__shfl_sync(~0u, ra1[i], k - 32));
        ull hv = dup2(__shfl_sync(~0u, rh1[i], k - 32));
        R[i]  = ffma2(av, wir, R[i]);  Z[i]  = ffma2(av, wiz, Z[i]);  Ng[i] = ffma2(av, win, Ng[i]);
        Rh[i] = ffma2(hv, whr, Rh[i]); Zh[i] = ffma2(hv, whz, Zh[i]); Nh[i] = ffma2(hv, whn, Nh[i]);
      }
    }
    float birL = sbi[lane],     birH = sbi[lane+32];
    float bizL = sbi[64+lane],  bizH = sbi[96+lane];
    float binL = sbi[128+lane], binH = sbi[160+lane];
    float bhrL = sbh[lane],     bhrH = sbh[lane+32];
    float bhzL = sbh[64+lane],  bhzH = sbh[96+lane];
    float bhnL = sbh[128+lane], bhnH = sbh[160+lane];
    #pragma unroll
    for (int i = 0; i < GNB; i++){
      int n = nbase + i;
      if (n >= NN) break;
      float rL,rH,zL,zH,ngL,ngH, aL,aH,bL,bH;
      unpk2(R[i],  aL, aH); unpk2(Rh[i], bL, bH);
      rL = sigf(aL + birL + bL + bhrL); rH = sigf(aH + birH + bH + bhrH);
      unpk2(Z[i],  aL, aH); unpk2(Zh[i], bL, bH);
      zL = sigf(aL + bizL + bL + bhzL); zH = sigf(aH + bizH + bH + bhzH);
      unpk2(Ng[i], aL, aH); unpk2(Nh[i], bL, bH);
      ngL = tanhf(aL + binL + rL*(bL + bhnL));
      ngH = tanhf(aH + binH + rH*(bH + bhnH));
      hout[(n<<6) + lane]      = (1.f - zL)*ngL + zL*rh0[i];
      hout[(n<<6) + 32 + lane] = (1.f - zH)*ngH + zH*rh1[i];
    }
  }
}

// ---------- decoder per-node A/B ----------
__global__ void k_AB(const float* __restrict__ hin,
                     const float* __restrict__ W1, const float* __restrict__ b1){
  __shared__ float sAt[H*65], sBt[H*65], sb[H];
  int t = threadIdx.x;
  for (int i = t; i < H*H; i += blockDim.x){
    int j = i >> 6, k = i & 63;
    sAt[k*65 + j] = W1[j*133 + k];
    sBt[k*65 + j] = W1[j*133 + 64 + k];
  }
  if (t < H) sb[t] = b1[t];
  __syncthreads();
  int lane = t & 31;
  int wg = (blockIdx.x*blockDim.x + t) >> 5;
  int nw = (gridDim.x*blockDim.x) >> 5;
  for (int n = wg; n < NN; n += nw){
    float v0 = hin[(n<<6) + lane], v1 = hin[(n<<6) + 32 + lane];
    float a0 = sb[lane], a1 = sb[32+lane], b0 = 0.f, b1v = 0.f;
    #pragma unroll
    for (int k = 0; k < 32; k++){
      float hk = __shfl_sync(0xffffffffu, v0, k);
      a0 = fmaf(hk, sAt[k*65 + lane], a0);      a1 = fmaf(hk, sAt[k*65 + 32 + lane], a1);
      b0 = fmaf(hk, sBt[k*65 + lane], b0);      b1v = fmaf(hk, sBt[k*65 + 32 + lane], b1v);
    }
    #pragma unroll
    for (int k = 0; k < 32; k++){
      float hk = __shfl_sync(0xffffffffu, v1, k);
      a0 = fmaf(hk, sAt[(32+k)*65 + lane], a0); a1 = fmaf(hk, sAt[(32+k)*65 + 32 + lane], a1);
      b0 = fmaf(hk, sBt[(32+k)*65 + lane], b0); b1v = fmaf(hk, sBt[(32+k)*65 + 32 + lane], b1v);
    }
    g_Ad[(n<<6) + lane]      = a0;  g_Ad[(n<<6) + 32 + lane] = a1;
    g_Bd[(n<<6) + lane]      = b0;  g_Bd[(n<<6) + 32 + lane] = b1v;
  }
}

// ---------- decoder ----------
__global__ void __launch_bounds__(256) k_dec(
    const float* __restrict__ ea, float* __restrict__ out,
    const float* __restrict__ b2, const float* __restrict__ W3,
    const float* __restrict__ b3){
  __shared__ __align__(16) ull sW1[160];
  __shared__ __align__(16) ull sW2[1024];
  __shared__ float4 sW3[32];
  __shared__ float sb2[32], sb3[4];
  __shared__ float sEA[1280];
  int t = threadIdx.x;
  int base = blockIdx.x*256;
  for (int i = t; i < 160;  i += blockDim.x) sW1[i] = g_W1e_p[i];
  for (int i = t; i < 1024; i += blockDim.x) sW2[i] = g_W2_p[i];
  {
    float* p3 = (float*)sW3;
    for (int i = t; i < 128; i += blockDim.x) p3[i] = W3[i];
  }
  if (t < 32) sb2[t] = b2[t];
  if (t < 4)  sb3[t] = b3[t];
  {
    int lim = MM*5 - base*5;
    for (int i = t; i < 1280 && i < lim; i += 256) sEA[i] = ea[base*5 + i];
  }
  __syncthreads();
  int e = base + t;
  if (e >= MM) return;
  int2 sd = g_sd[e];
  const float4* pA = (const float4*)&g_Ad[(size_t)sd.x << 6];
  const float4* pB = (const float4*)&g_Bd[(size_t)sd.y << 6];
  ull s1p[32];
  #pragma unroll
  for (int q = 0; q < 8; q++){
    float4 aL = __ldg(&pA[q]),   bL = __ldg(&pB[q]);
    float4 aH = __ldg(&pA[q+8]), bH = __ldg(&pB[q+8]);
    s1p[4*q]   = pk2(aL.x + bL.x, aH.x + bH.x);
    s1p[4*q+1] = pk2(aL.y + bL.y, aH.y + bH.y);
    s1p[4*q+2] = pk2(aL.z + bL.z, aH.z + bH.z);
    s1p[4*q+3] = pk2(aL.w + bL.w, aH.w + bH.w);
  }
  const ulonglong2* w1 = (const ulonglong2*)sW1;
  #pragma unroll
  for (int k = 0; k < 5; k++){
    ull ev = dup2(sEA[t*5 + k]);
    #pragma unroll
    for (int q = 0; q < 16; q++){
      ulonglong2 wq = w1[k*16 + q];
      s1p[2*q]   = ffma2(ev, wq.x, s1p[2*q]);
      s1p[2*q+1] = ffma2(ev, wq.y, s1p[2*q+1]);
    }
  }
  float s1[64];
  #pragma unroll
  for (int jp = 0; jp < 32; jp++){
    float lo, hi; unpk2(s1p[jp], lo, hi);
    s1[jp] = fmaxf(lo, 0.f); s1[jp+32] = fmaxf(hi, 0.f);
  }
  ull a2p[16];
  #pragma unroll
  for (int jp = 0; jp < 16; jp++) a2p[jp] = pk2(sb2[jp], sb2[jp+16]);
  const ulonglong2* w2 = (const ulonglong2*)sW2;
  #pragma unroll 8
  for (int k = 0; k < 64; k++){
    ull sdv = dup2(s1[k]);
    #pragma unroll
    for (int q = 0; q < 8; q++){
      ulonglong2 wq = w2[k*8 + q];
      a2p[2*q]   = ffma2(sdv, wq.x, a2p[2*q]);
      a2p[2*q+1] = ffma2(sdv, wq.y, a2p[2*q+1]);
    }
  }
  float a2[32];
  #pragma unroll
  for (int jp = 0; jp < 16; jp++){
    float lo, hi; unpk2(a2p[jp], lo, hi);
    a2[jp] = fmaxf(lo, 0.f); a2[jp+16] = fmaxf(hi, 0.f);
  }
  float o[4];
  #pragma unroll
  for (int j = 0; j < 4; j++){
    float acc = sb3[j];
    #pragma unroll
    for (int q = 0; q < 8; q++){
      float4 wv = sW3[j*8 + q];
      acc = fmaf(a2[4*q],   wv.x, acc);
      acc = fmaf(a2[4*q+1], wv.y, acc);
      acc = fmaf(a2[4*q+2], wv.z, acc);
      acc = fmaf(a2[4*q+3], wv.w, acc);
    }
    o[j] = acc;
  }
  ((float4*)out)[e] = make_float4(o[0], o[1], o[2], o[3]);
}

extern "C" void kernel_launch(void* const* d_in, const int* in_sizes, int n_in,
                              void* d_out, int out_size){
  (void)in_sizes; (void)n_in; (void)out_size;
  const float* x    = (const float*)d_in[0];
  const void*  ei   = d_in[1];
  const float* ea   = (const float*)d_in[2];
  const float* u    = (const float*)d_in[3];
  const float* Win  = (const float*)d_in[4];
  const float* bin  = (const float*)d_in[5];
  const float* eW1  = (const float*)d_in[6];
  const float* eb1  = (const float*)d_in[7];
  const float* eW2  = (const float*)d_in[8];
  const float* eb2  = (const float*)d_in[9];
  const float* msW  = (const float*)d_in[10];
  const float* msb  = (const float*)d_in[11];
  const float* Wih  = (const float*)d_in[12];
  const float* bih  = (const float*)d_in[13];
  const float* Whh  = (const float*)d_in[14];
  const float* bhh  = (const float*)d_in[15];
  const float* dW1  = (const float*)d_in[16];
  const float* db1  = (const float*)d_in[17];
  const float* dW2  = (const float*)d_in[18];
  const float* db2  = (const float*)d_in[19];
  const float* dW3  = (const float*)d_in[20];
  const float* db3  = (const float*)d_in[21];
  float* out = (float*)d_out;

  static int init_done = 0;
  static cudaStream_t s1;
  static cudaEvent_t evA, evB;
  if (!init_done){
    cudaFuncSetAttribute(k_gru, cudaFuncAttributeMaxDynamicSharedMemorySize, GRU_SMEM);
    cudaStreamCreateWithFlags(&s1, cudaStreamNonBlocking);
    cudaEventCreateWithFlags(&evA, cudaEventDisableTiming);
    cudaEventCreateWithFlags(&evB, cudaEventDisableTiming);
    init_done = 1;
  }

  float *hA_p = nullptr, *hB_p = nullptr;
  __half2 *hmA_p = nullptr, *hmB_p = nullptr;
  cudaGetSymbolAddress((void**)&hA_p, g_hA);
  cudaGetSymbolAddress((void**)&hB_p, g_hB);
  cudaGetSymbolAddress((void**)&hmA_p, g_hmA);
  cudaGetSymbolAddress((void**)&hmB_p, g_hmB);

  // prologue
  k_init<<<235, 256>>>((const int*)ei, Wih, Whh, dW2, dW1, msW, eW1, eb1, eW2, Win, bin, u);

  cudaEventRecord(evA, 0);
  cudaStreamWaitEvent(s1, evA, 0);

  // node chain on s1
  k_h2<<<(NN*H + 255)/256, 256, 0, s1>>>(x, Win);
  k_hm<<<1184, 256, 0, s1>>>(hA_p, hmA_p, msb);
  cudaEventRecord(evB, s1);

  // edge chain on default stream
  k_count<<<(MM + 255)/256, 256>>>(ei);
  k_scan1<<<SCB, 256>>>();
  k_scan2<<<1, 256>>>();
  k_scan3<<<SCB, 256>>>();
  k_prep2<<<(MM + 255)/256, 256>>>(ei, ea, eb2);

  cudaStreamWaitEvent(0, evB, 0);

  const int GRID_AGG = (NN*32 + 255)/256;
  k_agg<<<GRID_AGG, 256>>>(hmA_p);
  k_gru<<<296, 256, GRU_SMEM>>>(hA_p, hB_p, bih, bhh);

  k_hm<<<1184, 256>>>(hB_p, hmB_p, msb);
  k_agg<<<GRID_AGG, 256>>>(hmB_p);
  k_gru<<<296, 256, GRU_SMEM>>>(hB_p, hA_p, bih, bhh);

  k_hm<<<1184, 256>>>(hA_p, hmA_p, msb);
  k_agg<<<GRID_AGG, 256>>>(hmA_p);
  k_gru<<<296, 256, GRU_SMEM>>>(hA_p, hB_p, bih, bhh);

  k_AB<<<1184, 256>>>(hB_p, dW1, db1);
  k_dec<<<(MM + 255)/256, 256>>>(ea, out, db2, dW3, db3);
}

// round 10
// speedup vs baseline: 1.1328x; 1.0569x over previous
#include <cuda_runtime.h>
#include <cuda_fp16.h>
#include <math.h>

#define NN 50000
#define MM 1250000
#define H  64

typedef unsigned long long ull;

__device__ float g_hA[NN*H];
__device__ float g_hB[NN*H];
__device__ float g_agg[NN*H];
__device__ __half2 g_hmA[NN*32];
__device__ __half2 g_hmB[NN*32];
__device__ __half2 g_Adh[NN*32];
__device__ __half2 g_Bdh[NN*32];
__device__ int2  g_sd[MM];
__device__ int2  g_csr[MM];
__device__ int   g_cnt[NN];
__device__ int   g_rowptr[NN+1];
__device__ int   g_cursor[NN];
__device__ int   g_is64;
__device__ int   g_bsum[256];
__device__ int   g_boff[256];
// packed tables
__device__ ull g_Wih_p[64*3*32];
__device__ ull g_Whh_p[64*3*32];
__device__ ull g_W2_p[64*16];    // pairs (2jp, 2jp+1) at k*16+jp
__device__ ull g_W1e_p[5*32];    // pairs (2p, 2p+1) at k*32+p
__device__ ull g_Whm_p[64*32];   // pairs (2l, 2l+1) at k*32+l
__device__ ull g_Wa_p[64*32];    // dW1 cols 0..63, pairs (2l,2l+1)
__device__ ull g_Wb_p[64*32];    // dW1 cols 64..127
__device__ ull g_We_p[5*16];
__device__ float g_b1e[32];
__device__ float g_W2e[32];
__device__ float g_bhe[64];

__device__ __forceinline__ float sigf(float x){ return 1.f/(1.f+__expf(-x)); }
__device__ __forceinline__ ull ffma2(ull a, ull b, ull c){
  ull d; asm("fma.rn.f32x2 %0, %1, %2, %3;" : "=l"(d) : "l"(a), "l"(b), "l"(c)); return d;
}
__device__ __forceinline__ ull dup2(float v){
  ull r; asm("mov.b64 %0, {%1, %1};" : "=l"(r) : "f"(v)); return r;
}
__device__ __forceinline__ ull pk2(float lo, float hi){
  ull r; asm("mov.b64 %0, {%1, %2};" : "=l"(r) : "f"(lo), "f"(hi)); return r;
}
__device__ __forceinline__ void unpk2(ull p, float& lo, float& hi){
  asm("mov.b64 {%0, %1}, %2;" : "=f"(lo), "=f"(hi) : "l"(p));
}

// ---------- merged prologue ----------
__global__ void k_init(const int* __restrict__ ei,
                       const float* __restrict__ Wih, const float* __restrict__ Whh,
                       const float* __restrict__ dW2, const float* __restrict__ dW1,
                       const float* __restrict__ msW,
                       const float* __restrict__ eW1, const float* __restrict__ eb1,
                       const float* __restrict__ eW2,
                       const float* __restrict__ Win, const float* __restrict__ bin,
                       const float* __restrict__ u){
  int b = blockIdx.x, t = threadIdx.x;
  if (b < 196){
    int i = b*256 + t;
    if (i < NN) g_cnt[i] = 0;
  } else if (b == 196){
    __shared__ int nz;
    if (t == 0) nz = 0;
    __syncthreads();
    int c = 0;
    for (int i = t; i < 4096; i += 256) c += (ei[2*i+1] != 0);
    if (c) atomicAdd(&nz, 1);
    __syncthreads();
    if (t == 0) g_is64 = (nz == 0);
  } else if (b < 226){
    int i = (b-197)*256 + t;
    if (i < 6144){
      int jp = i & 31, r = i >> 5, g = r % 3, k = r / 3;
      g_Wih_p[i] = pk2(Wih[(g*64+jp)*64 + k], Wih[(g*64+jp+32)*64 + k]);
      g_Whh_p[i] = pk2(Whh[(g*64+jp)*64 + k], Whh[(g*64+jp+32)*64 + k]);
    } else if (i < 7168){
      int q = i - 6144;
      int jp = q & 15, k = q >> 4;
      g_W2_p[q] = pk2(dW2[(2*jp)*64 + k], dW2[(2*jp+1)*64 + k]);
    } else if (i < 7328){
      int q = i - 7168;
      int jp = q & 31, k = q >> 5;
      g_W1e_p[q] = pk2(dW1[(2*jp)*133 + 128 + k], dW1[(2*jp+1)*133 + 128 + k]);
    }
  } else if (b < 235){
    int i = (b-226)*256 + t;
    if (i < 2048){
      int l = i & 31, k = i >> 5;
      g_Whm_p[i] = pk2(msW[(2*l)*64 + k], msW[(2*l+1)*64 + k]);
    } else if (i < 2128){
      int q = i - 2048;
      int ip = q & 15, k = q >> 4;
      g_We_p[q] = pk2(eW1[ip*16 + k], eW1[(ip+16)*16 + k]);
    } else if (i < 2160){
      int q = i - 2128;
      float acc = eb1[q];
      #pragma unroll
      for (int k = 0; k < 11; k++) acc = fmaf(u[k], eW1[q*16 + 5 + k], acc);
      g_b1e[q] = acc;
      g_W2e[q] = eW2[q];
    } else if (i < 2224){
      int j = i - 2160;
      float acc = bin[j];
      #pragma unroll
      for (int k = 0; k < 11; k++) acc = fmaf(u[k], Win[j*23 + 12 + k], acc);
      g_bhe[j] = acc;
    }
  } else {
    int i = (b-235)*256 + t;
    if (i < 2048){
      int l = i & 31, k = i >> 5;
      g_Wa_p[i] = pk2(dW1[(2*l)*133 + k], dW1[(2*l+1)*133 + k]);
    } else if (i < 4096){
      int q = i - 2048;
      int l = q & 31, k = q >> 5;
      g_Wb_p[q] = pk2(dW1[(2*l)*133 + 64 + k], dW1[(2*l+1)*133 + 64 + k]);
    }
  }
}

// ---------- histogram ----------
__global__ void __launch_bounds__(256) k_count(const void* __restrict__ ei){
  int e = blockIdx.x*blockDim.x + threadIdx.x;
  if (e >= MM) return;
  int d;
  if (g_is64) d = (int)((const long long*)ei)[MM + e];
  else        d = ((const int*)ei)[MM + e];
  atomicAdd(&g_cnt[d], 1);
}

#define SCB 196
__global__ void k_scan1(){
  int b = blockIdx.x, t = threadIdx.x;
  int i = b*256 + t;
  int v = (i < NN) ? g_cnt[i] : 0;
  __shared__ int ws[8];
  int lane = t & 31, wid = t >> 5;
  #pragma unroll
  for (int o = 16; o >= 1; o >>= 1) v += __shfl_down_sync(~0u, v, o);
  if (lane == 0) ws[wid] = v;
  __syncthreads();
  if (t == 0){
    int s = 0;
    #pragma unroll
    for (int w = 0; w < 8; w++) s += ws[w];
    g_bsum[b] = s;
  }
}
__global__ void k_scan2(){
  int t = threadIdx.x;
  int v = (t < SCB) ? g_bsum[t] : 0;
  int lane = t & 31, wid = t >> 5;
  __shared__ int ws[8], wo[8];
  int x = v;
  #pragma unroll
  for (int o = 1; o < 32; o <<= 1){ int u = __shfl_up_sync(~0u, x, o); if (lane >= o) x += u; }
  if (lane == 31) ws[wid] = x;
  __syncthreads();
  if (t == 0){
    int s = 0;
    #pragma unroll
    for (int w = 0; w < 8; w++){ wo[w] = s; s += ws[w]; }
  }
  __syncthreads();
  g_boff[t] = x - v + wo[wid];
}
__global__ void k_scan3(){
  int b = blockIdx.x, t = threadIdx.x;
  int i = b*256 + t;
  int v = (i < NN) ? g_cnt[i] : 0;
  int lane = t & 31, wid = t >> 5;
  __shared__ int ws[8], wo[8];
  int x = v;
  #pragma unroll
  for (int o = 1; o < 32; o <<= 1){ int u = __shfl_up_sync(~0u, x, o); if (lane >= o) x += u; }
  if (lane == 31) ws[wid] = x;
  __syncthreads();
  if (t == 0){
    int s = 0;
    #pragma unroll
    for (int w = 0; w < 8; w++){ wo[w] = s; s += ws[w]; }
  }
  __syncthreads();
  int excl = x - v + wo[wid] + g_boff[b];
  if (i < NN){ g_cursor[i] = excl; g_rowptr[i+1] = excl + v; }
  if (i == 0) g_rowptr[0] = 0;
}

// ---------- alpha + direct CSR write ----------
__global__ void __launch_bounds__(256) k_prep2(
    const void* __restrict__ ei, const float* __restrict__ ea,
    const float* __restrict__ b2){
  __shared__ float sEA[1280];
  __shared__ ull sWe[80], sB1[16];
  __shared__ float sW2[32];
  __shared__ float sb2;
  int t = threadIdx.x;
  int base = blockIdx.x*256;
  for (int i = t; i < 80; i += 256) sWe[i] = g_We_p[i];
  if (t < 16) sB1[t] = pk2(g_b1e[t], g_b1e[t+16]);
  if (t < 32) sW2[t] = g_W2e[t];
  if (t == 0) sb2 = b2[0];
  {
    int lim = MM*5 - base*5;
    for (int i = t; i < 1280 && i < lim; i += 256) sEA[i] = ea[base*5 + i];
  }
  __syncthreads();
  int e = base + t;
  if (e >= MM) return;
  int s, d;
  if (g_is64){
    const long long* p = (const long long*)ei;
    s = (int)p[e]; d = (int)p[MM + e];
  } else {
    const int* p = (const int*)ei;
    s = p[e]; d = p[MM + e];
  }
  g_sd[e] = make_int2(s, d);
  float f[5];
  #pragma unroll
  for (int k = 0; k < 5; k++) f[k] = sEA[t*5 + k];
  ull ap[16];
  #pragma unroll
  for (int i = 0; i < 16; i++) ap[i] = sB1[i];
  #pragma unroll
  for (int k = 0; k < 5; k++){
    ull fv = dup2(f[k]);
    #pragma unroll
    for (int i = 0; i < 16; i++) ap[i] = ffma2(fv, sWe[k*16 + i], ap[i]);
  }
  float acc = sb2;
  #pragma unroll
  for (int i = 0; i < 16; i++){
    float lo, hi; unpk2(ap[i], lo, hi);
    acc = fmaf(fmaxf(lo, 0.f), sW2[i], acc);
    acc = fmaf(fmaxf(hi, 0.f), sW2[i+16], acc);
  }
  int p = atomicAdd(&g_cursor[d], 1);
  g_csr[p] = make_int2(s, __float_as_int(sigf(acc)));
}

// ---------- input projection ----------
__global__ void k_h2(const float* __restrict__ x, const float* __restrict__ Win){
  __shared__ float sW[64*12], sb[64];
  int t = threadIdx.x;
  for (int i = t; i < 64*12; i += blockDim.x){ int j = i/12, k = i%12; sW[i] = Win[j*23 + k]; }
  if (t < 64) sb[t] = g_bhe[t];
  __syncthreads();
  int idx = blockIdx.x*blockDim.x + t;
  if (idx >= NN*H) return;
  int node = idx >> 6, j = idx & 63;
  const float* w = &sW[j*12];
  const float* xr = &x[node*12];
  float acc = sb[j];
  #pragma unroll
  for (int k = 0; k < 12; k++) acc = fmaf(xr[k], w[k], acc);
  g_hA[idx] = tanhf(acc);
}

// ---------- initial hm ----------
__global__ void k_hm0(const float* __restrict__ hin, __half2* __restrict__ hmout,
                      const float* __restrict__ b){
  __shared__ ull sW[64*32];
  __shared__ ull sbp[32];
  int t = threadIdx.x;
  for (int i = t; i < 2048; i += blockDim.x) sW[i] = g_Whm_p[i];
  if (t < 32) sbp[t] = pk2(b[2*t], b[2*t+1]);
  __syncthreads();
  int lane = t & 31;
  int wg = (blockIdx.x*blockDim.x + t) >> 5;
  int nw = (gridDim.x*blockDim.x) >> 5;
  for (int n = wg; n < NN; n += nw){
    float v0 = hin[(n<<6) + lane], v1 = hin[(n<<6) + 32 + lane];
    ull ap = sbp[lane];
    #pragma unroll 8
    for (int k = 0; k < 32; k++)
      ap = ffma2(dup2(__shfl_sync(~0u, v0, k)), sW[k*32 + lane], ap);
    #pragma unroll 8
    for (int k = 0; k < 32; k++)
      ap = ffma2(dup2(__shfl_sync(~0u, v1, k)), sW[(32+k)*32 + lane], ap);
    float lo, hi; unpk2(ap, lo, hi);
    hmout[n*32 + lane] = __floats2half2_rn(fmaxf(lo, 0.f), fmaxf(hi, 0.f));
  }
}

// ---------- aggregation ----------
__global__ void k_agg(const __half2* __restrict__ hmin){
  int w = (blockIdx.x*blockDim.x + threadIdx.x) >> 5;
  int lane = threadIdx.x & 31;
  if (w >= NN) return;
  int beg = g_rowptr[w], end = g_rowptr[w+1];
  float ax = 0.f, ay = 0.f;
  int i = beg;
  for (; i + 3 < end; i += 4){
    int2 e0 = g_csr[i], e1 = g_csr[i+1], e2 = g_csr[i+2], e3 = g_csr[i+3];
    float2 f0 = __half22float2(hmin[(size_t)e0.x*32 + lane]);
    float2 f1 = __half22float2(hmin[(size_t)e1.x*32 + lane]);
    float2 f2 = __half22float2(hmin[(size_t)e2.x*32 + lane]);
    float2 f3 = __half22float2(hmin[(size_t)e3.x*32 + lane]);
    float a0 = __int_as_float(e0.y), a1 = __int_as_float(e1.y);
    float a2 = __int_as_float(e2.y), a3 = __int_as_float(e3.y);
    ax = fmaf(a0, f0.x, ax); ay = fmaf(a0, f0.y, ay);
    ax = fmaf(a1, f1.x, ax); ay = fmaf(a1, f1.y, ay);
    ax = fmaf(a2, f2.x, ax); ay = fmaf(a2, f2.y, ay);
    ax = fmaf(a3, f3.x, ax); ay = fmaf(a3, f3.y, ay);
  }
  for (; i < end; i++){
    int2 e0 = g_csr[i];
    float a0 = __int_as_float(e0.y);
    float2 f0 = __half22float2(hmin[(size_t)e0.x*32 + lane]);
    ax = fmaf(a0, f0.x, ax); ay = fmaf(a0, f0.y, ay);
  }
  float inv = 1.f / fmaxf((float)(end - beg), 1.f);
  ((float2*)g_agg)[w*32 + lane] = make_float2(ax*inv, ay*inv);
}

// NOTE: agg writes feature pair (2*lane, 2*lane+1) at float2 slot [w*32+lane]
// => g_agg[n*64 + f] natural layout.

// ---------- GRU core macro shared by both variants ----------
#define GNB 4
#define GRU_BODY(RA0,RA1,RH0,RH1)                                                   \
    ull R[GNB], Z[GNB], Ng[GNB], Rh[GNB], Zh[GNB], Nh[GNB];                         \
    _Pragma("unroll")                                                               \
    for (int i = 0; i < GNB; i++){ R[i]=Z[i]=Ng[i]=Rh[i]=Zh[i]=Nh[i]=0ull; }        \
    _Pragma("unroll 4")                                                             \
    for (int k = 0; k < 32; k++){                                                   \
      ull wir = sWi[(k*3+0)*32 + lane], wiz = sWi[(k*3+1)*32 + lane], win = sWi[(k*3+2)*32 + lane]; \
      ull whr = sWh[(k*3+0)*32 + lane], whz = sWh[(k*3+1)*32 + lane], whn = sWh[(k*3+2)*32 + lane]; \
      _Pragma("unroll")                                                             \
      for (int i = 0; i < GNB; i++){                                                \
        ull av = dup2(__shfl_sync(~0u, RA0[i], k));                                 \
        ull hv = dup2(__shfl_sync(~0u, RH0[i], k));                                 \
        R[i]  = ffma2(av, wir, R[i]);  Z[i]  = ffma2(av, wiz, Z[i]);  Ng[i] = ffma2(av, win, Ng[i]); \
        Rh[i] = ffma2(hv, whr, Rh[i]); Zh[i] = ffma2(hv, whz, Zh[i]); Nh[i] = ffma2(hv, whn, Nh[i]); \
      }                                                                             \
    }                                                                               \
    _Pragma("unroll 4")                                                             \
    for (int k = 32; k < 64; k++){                                                  \
      ull wir = sWi[(k*3+0)*32 + lane], wiz = sWi[(k*3+1)*32 + lane], win = sWi[(k*3+2)*32 + lane]; \
      ull whr = sWh[(k*3+0)*32 + lane], whz = sWh[(k*3+1)*32 + lane], whn = sWh[(k*3+2)*32 + lane]; \
      _Pragma("unroll")                                                             \
      for (int i = 0; i < GNB; i++){                                                \
        ull av = dup2(__shfl_sync(~0u, RA1[i], k - 32));                            \
        ull hv = dup2(__shfl_sync(~0u, RH1[i], k - 32));                            \
        R[i]  = ffma2(av, wir, R[i]);  Z[i]  = ffma2(av, wiz, Z[i]);  Ng[i] = ffma2(av, win, Ng[i]); \
        Rh[i] = ffma2(hv, whr, Rh[i]); Zh[i] = ffma2(hv, whz, Zh[i]); Nh[i] = ffma2(hv, whn, Nh[i]); \
      }                                                                             \
    }

// ---------- GRU + fused hm (steps 1,2) ----------
#define GRUF_SMEM ((6144+6144+2048)*8)
__global__ void __launch_bounds__(256,2) k_gruf(
    const float* __restrict__ hin, float* __restrict__ hout,
    __half2* __restrict__ hmout,
    const float* __restrict__ bih, const float* __restrict__ bhh,
    const float* __restrict__ msb){
  extern __shared__ ull sw[];
  ull* sWi = sw;
  ull* sWh = sw + 6144;
  ull* sHm = sw + 12288;
  __shared__ float sbi[192], sbh[192];
  __shared__ ull sMb[32];
  int t = threadIdx.x;
  for (int i = t; i < 6144; i += 256){ sWi[i] = g_Wih_p[i]; sWh[i] = g_Whh_p[i]; }
  for (int i = t; i < 2048; i += 256) sHm[i] = g_Whm_p[i];
  for (int i = t; i < 192; i += 256){ sbi[i] = bih[i]; sbh[i] = bhh[i]; }
  if (t < 32) sMb[t] = pk2(msb[2*t], msb[2*t+1]);
  __syncthreads();
  int w = t >> 5, lane = t & 31;
  int nchunk = (NN + 31) / 32;
  for (int c = blockIdx.x; c < nchunk; c += gridDim.x){
    int nbase = c*32 + w*GNB;
    float ra0[GNB], ra1[GNB], rh0[GNB], rh1[GNB];
    #pragma unroll
    for (int i = 0; i < GNB; i++){
      int n = min(nbase + i, NN - 1);
      ra0[i] = g_agg[(n<<6) + lane];  ra1[i] = g_agg[(n<<6) + 32 + lane];
      rh0[i] = hin[(n<<6) + lane];    rh1[i] = hin[(n<<6) + 32 + lane];
    }
    GRU_BODY(ra0, ra1, rh0, rh1)
    float birL = sbi[lane],     birH = sbi[lane+32];
    float bizL = sbi[64+lane],  bizH = sbi[96+lane];
    float binL = sbi[128+lane], binH = sbi[160+lane];
    float bhrL = sbh[lane],     bhrH = sbh[lane+32];
    float bhzL = sbh[64+lane],  bhzH = sbh[96+lane];
    float bhnL = sbh[128+lane], bhnH = sbh[160+lane];
    #pragma unroll
    for (int i = 0; i < GNB; i++){
      int n = nbase + i;
      bool ok = (n < NN);
      float rL,rH,zL,zH,ngL,ngH, aL,aH,bL,bH;
      unpk2(R[i],  aL, aH); unpk2(Rh[i], bL, bH);
      rL = sigf(aL + birL + bL + bhrL); rH = sigf(aH + birH + bH + bhrH);
      unpk2(Z[i],  aL, aH); unpk2(Zh[i], bL, bH);
      zL = sigf(aL + bizL + bL + bhzL); zH = sigf(aH + bizH + bH + bhzH);
      unpk2(Ng[i], aL, aH); unpk2(Nh[i], bL, bH);
      ngL = tanhf(aL + binL + rL*(bL + bhnL));
      ngH = tanhf(aH + binH + rH*(bH + bhnH));
      float hnL = (1.f - zL)*ngL + zL*rh0[i];
      float hnH = (1.f - zH)*ngH + zH*rh1[i];
      if (ok){
        hout[(n<<6) + lane]      = hnL;
        hout[(n<<6) + 32 + lane] = hnH;
      }
      // fused hm: relu(hn @ msW.T + msb) -> half2, pairs (2*lane, 2*lane+1)
      ull ap = sMb[lane];
      #pragma unroll 8
      for (int k = 0; k < 32; k++)
        ap = ffma2(dup2(__shfl_sync(~0u, hnL, k)), sHm[k*32 + lane], ap);
      #pragma unroll 8
      for (int k = 0; k < 32; k++)
        ap = ffma2(dup2(__shfl_sync(~0u, hnH, k)), sHm[(32+k)*32 + lane], ap);
      float lo, hi; unpk2(ap, lo, hi);
      if (ok) hmout[n*32 + lane] = __floats2half2_rn(fmaxf(lo, 0.f), fmaxf(hi, 0.f));
    }
  }
}

// ---------- plain GRU (last step) ----------
#define GRU_SMEM (2*6144*8)
__global__ void __launch_bounds__(256,2) k_gru(
    const float* __restrict__ hin, float* __restrict__ hout,
    const float* __restrict__ bih, const float* __restrict__ bhh){
  extern __shared__ ull sw[];
  ull* sWi = sw;
  ull* sWh = sw + 6144;
  __shared__ float sbi[192], sbh[192];
  int t = threadIdx.x;
  for (int i = t; i < 6144; i += 256){ sWi[i] = g_Wih_p[i]; sWh[i] = g_Whh_p[i]; }
  for (int i = t; i < 192; i += 256){ sbi[i] = bih[i]; sbh[i] = bhh[i]; }
  __syncthreads();
  int w = t >> 5, lane = t & 31;
  int nchunk = (NN + 31) / 32;
  for (int c = blockIdx.x; c < nchunk; c += gridDim.x){
    int nbase = c*32 + w*GNB;
    float ra0[GNB], ra1[GNB], rh0[GNB], rh1[GNB];
    #pragma unroll
    for (int i = 0; i < GNB; i++){
      int n = min(nbase + i, NN - 1);
      ra0[i] = g_agg[(n<<6) + lane];  ra1[i] = g_agg[(n<<6) + 32 + lane];
      rh0[i] = hin[(n<<6) + lane];    rh1[i] = hin[(n<<6) + 32 + lane];
    }
    GRU_BODY(ra0, ra1, rh0, rh1)
    float birL = sbi[lane],     birH = sbi[lane+32];
    float bizL = sbi[64+lane],  bizH = sbi[96+lane];
    float binL = sbi[128+lane], binH = sbi[160+lane];
    float bhrL = sbh[lane],     bhrH = sbh[lane+32];
    float bhzL = sbh[64+lane],  bhzH = sbh[96+lane];
    float bhnL = sbh[128+lane], bhnH = sbh[160+lane];
    #pragma unroll
    for (int i = 0; i < GNB; i++){
      int n = nbase + i;
      if (n >= NN) break;
      float rL,rH,zL,zH,ngL,ngH, aL,aH,bL,bH;
      unpk2(R[i],  aL, aH); unpk2(Rh[i], bL, bH);
      rL = sigf(aL + birL + bL + bhrL); rH = sigf(aH + birH + bH + bhrH);
      unpk2(Z[i],  aL, aH); unpk2(Zh[i], bL, bH);
      zL = sigf(aL + bizL + bL + bhzL); zH = sigf(aH + bizH + bH + bhzH);
      unpk2(Ng[i], aL, aH); unpk2(Nh[i], bL, bH);
      ngL = tanhf(aL + binL + rL*(bL + bhnL));
      ngH = tanhf(aH + binH + rH*(bH + bhnH));
      hout[(n<<6) + lane]      = (1.f - zL)*ngL + zL*rh0[i];
      hout[(n<<6) + 32 + lane] = (1.f - zH)*ngH + zH*rh1[i];
    }
  }
}

// ---------- decoder per-node A/B -> half2, pairs (2l, 2l+1) ----------
__global__ void k_AB(const float* __restrict__ hin, const float* __restrict__ b1){
  __shared__ ull sWa[2048], sWb[2048];
  __shared__ ull sbp[32];
  int t = threadIdx.x;
  for (int i = t; i < 2048; i += blockDim.x){ sWa[i] = g_Wa_p[i]; sWb[i] = g_Wb_p[i]; }
  if (t < 32) sbp[t] = pk2(b1[2*t], b1[2*t+1]);
  __syncthreads();
  int lane = t & 31;
  int wg = (blockIdx.x*blockDim.x + t) >> 5;
  int nw = (gridDim.x*blockDim.x) >> 5;
  for (int n = wg; n < NN; n += nw){
    float v0 = hin[(n<<6) + lane], v1 = hin[(n<<6) + 32 + lane];
    ull aA = sbp[lane], aB = 0ull;
    #pragma unroll 8
    for (int k = 0; k < 32; k++){
      ull v = dup2(__shfl_sync(~0u, v0, k));
      aA = ffma2(v, sWa[k*32 + lane], aA);
      aB = ffma2(v, sWb[k*32 + lane], aB);
    }
    #pragma unroll 8
    for (int k = 0; k < 32; k++){
      ull v = dup2(__shfl_sync(~0u, v1, k));
      aA = ffma2(v, sWa[(32+k)*32 + lane], aA);
      aB = ffma2(v, sWb[(32+k)*32 + lane], aB);
    }
    float alo, ahi, blo, bhi;
    unpk2(aA, alo, ahi); unpk2(aB, blo, bhi);
    g_Adh[n*32 + lane] = __floats2half2_rn(alo, ahi);
    g_Bdh[n*32 + lane] = __floats2half2_rn(blo, bhi);
  }
}

// ---------- decoder (fp16 A/B gathers, pairs (2p,2p+1)) ----------
__global__ void __launch_bounds__(256) k_dec(
    const float* __restrict__ ea, float* __restrict__ out,
    const float* __restrict__ b2, const float* __restrict__ W3,
    const float* __restrict__ b3){
  __shared__ __align__(16) ull sW1[160];
  __shared__ __align__(16) ull sW2[1024];
  __shared__ float4 sW3[32];
  __shared__ float sb2[32], sb3[4];
  __shared__ float sEA[1280];
  int t = threadIdx.x;
  int base = blockIdx.x*256;
  for (int i = t; i < 160;  i += blockDim.x) sW1[i] = g_W1e_p[i];
  for (int i = t; i < 1024; i += blockDim.x) sW2[i] = g_W2_p[i];
  {
    float* p3 = (float*)sW3;
    for (int i = t; i < 128; i += blockDim.x) p3[i] = W3[i];
  }
  if (t < 32) sb2[t] = b2[t];
  if (t < 4)  sb3[t] = b3[t];
  {
    int lim = MM*5 - base*5;
    for (int i = t; i < 1280 && i < lim; i += 256) sEA[i] = ea[base*5 + i];
  }
  __syncthreads();
  int e = base + t;
  if (e >= MM) return;
  int2 sd = g_sd[e];
  const uint4* pA = (const uint4*)&g_Adh[(size_t)sd.x*32];
  const uint4* pB = (const uint4*)&g_Bdh[(size_t)sd.y*32];
  // s1p[p] = features (2p, 2p+1)
  ull s1p[32];
  #pragma unroll
  for (int q = 0; q < 8; q++){
    uint4 av = __ldg(&pA[q]);
    uint4 bv = __ldg(&pB[q]);
    float2 fa, fb;
    fa = __half22float2(*(__half2*)&av.x); fb = __half22float2(*(__half2*)&bv.x);
    s1p[4*q+0] = pk2(fa.x + fb.x, fa.y + fb.y);
    fa = __half22float2(*(__half2*)&av.y); fb = __half22float2(*(__half2*)&bv.y);
    s1p[4*q+1] = pk2(fa.x + fb.x, fa.y + fb.y);
    fa = __half22float2(*(__half2*)&av.z); fb = __half22float2(*(__half2*)&bv.z);
    s1p[4*q+2] = pk2(fa.x + fb.x, fa.y + fb.y);
    fa = __half22float2(*(__half2*)&av.w); fb = __half22float2(*(__half2*)&bv.w);
    s1p[4*q+3] = pk2(fa.x + fb.x, fa.y + fb.y);
  }
  const ulonglong2* w1 = (const ulonglong2*)sW1;
  #pragma unroll
  for (int k = 0; k < 5; k++){
    ull ev = dup2(sEA[t*5 + k]);
    #pragma unroll
    for (int q = 0; q < 16; q++){
      ulonglong2 wq = w1[k*16 + q];
      s1p[2*q]   = ffma2(ev, wq.x, s1p[2*q]);
      s1p[2*q+1] = ffma2(ev, wq.y, s1p[2*q+1]);
    }
  }
  float s1[64];
  #pragma unroll
  for (int p = 0; p < 32; p++){
    float lo, hi; unpk2(s1p[p], lo, hi);
    s1[2*p] = fmaxf(lo, 0.f); s1[2*p+1] = fmaxf(hi, 0.f);
  }
  // layer 2: a2p[jp] = outputs (2jp, 2jp+1)
  ull a2p[16];
  #pragma unroll
  for (int jp = 0; jp < 16; jp++) a2p[jp] = pk2(sb2[2*jp], sb2[2*jp+1]);
  const ulonglong2* w2 = (const ulonglong2*)sW2;
  #pragma unroll 8
  for (int k = 0; k < 64; k++){
    ull sdv = dup2(s1[k]);
    #pragma unroll
    for (int q = 0; q < 8; q++){
      ulonglong2 wq = w2[k*8 + q];
      a2p[2*q]   = ffma2(sdv, wq.x, a2p[2*q]);
      a2p[2*q+1] = ffma2(sdv, wq.y, a2p[2*q+1]);
    }
  }
  float a2[32];
  #pragma unroll
  for (int jp = 0; jp < 16; jp++){
    float lo, hi; unpk2(a2p[jp], lo, hi);
    a2[2*jp] = fmaxf(lo, 0.f); a2[2*jp+1] = fmaxf(hi, 0.f);
  }
  float o[4];
  #pragma unroll
  for (int j = 0; j < 4; j++){
    float acc = sb3[j];
    #pragma unroll
    for (int q = 0; q < 8; q++){
      float4 wv = sW3[j*8 + q];
      acc = fmaf(a2[4*q],   wv.x, acc);
      acc = fmaf(a2[4*q+1], wv.y, acc);
      acc = fmaf(a2[4*q+2], wv.z, acc);
      acc = fmaf(a2[4*q+3], wv.w, acc);
    }
    o[j] = acc;
  }
  ((float4*)out)[e] = make_float4(o[0], o[1], o[2], o[3]);
}

extern "C" void kernel_launch(void* const* d_in, const int* in_sizes, int n_in,
                              void* d_out, int out_size){
  (void)in_sizes; (void)n_in; (void)out_size;
  const float* x    = (const float*)d_in[0];
  const void*  ei   = d_in[1];
  const float* ea   = (const float*)d_in[2];
  const float* u    = (const float*)d_in[3];
  const float* Win  = (const float*)d_in[4];
  const float* bin  = (const float*)d_in[5];
  const float* eW1  = (const float*)d_in[6];
  const float* eb1  = (const float*)d_in[7];
  const float* eW2  = (const float*)d_in[8];
  const float* eb2  = (const float*)d_in[9];
  const float* msW  = (const float*)d_in[10];
  const float* msb  = (const float*)d_in[11];
  const float* Wih  = (const float*)d_in[12];
  const float* bih  = (const float*)d_in[13];
  const float* Whh  = (const float*)d_in[14];
  const float* bhh  = (const float*)d_in[15];
  const float* dW1  = (const float*)d_in[16];
  const float* db1  = (const float*)d_in[17];
  const float* dW2  = (const float*)d_in[18];
  const float* db2  = (const float*)d_in[19];
  const float* dW3  = (const float*)d_in[20];
  const float* db3  = (const float*)d_in[21];
  float* out = (float*)d_out;

  static int init_done = 0;
  static cudaStream_t s1;
  static cudaEvent_t evA, evB;
  if (!init_done){
    cudaFuncSetAttribute(k_gru,  cudaFuncAttributeMaxDynamicSharedMemorySize, GRU_SMEM);
    cudaFuncSetAttribute(k_gruf, cudaFuncAttributeMaxDynamicSharedMemorySize, GRUF_SMEM);
    cudaStreamCreateWithFlags(&s1, cudaStreamNonBlocking);
    cudaEventCreateWithFlags(&evA, cudaEventDisableTiming);
    cudaEventCreateWithFlags(&evB, cudaEventDisableTiming);
    init_done = 1;
  }

  float *hA_p = nullptr, *hB_p = nullptr;
  __half2 *hmA_p = nullptr, *hmB_p = nullptr;
  cudaGetSymbolAddress((void**)&hA_p, g_hA);
  cudaGetSymbolAddress((void**)&hB_p, g_hB);
  cudaGetSymbolAddress((void**)&hmA_p, g_hmA);
  cudaGetSymbolAddress((void**)&hmB_p, g_hmB);

  // prologue
  k_init<<<251, 256>>>((const int*)ei, Wih, Whh, dW2, dW1, msW, eW1, eb1, eW2, Win, bin, u);

  cudaEventRecord(evA, 0);
  cudaStreamWaitEvent(s1, evA, 0);

  // node chain on s1
  k_h2<<<(NN*H + 255)/256, 256, 0, s1>>>(x, Win);
  k_hm0<<<1184, 256, 0, s1>>>(hA_p, hmA_p, msb);
  cudaEventRecord(evB, s1);

  // edge chain on default stream
  k_count<<<(MM + 255)/256, 256>>>(ei);
  k_scan1<<<SCB, 256>>>();
  k_scan2<<<1, 256>>>();
  k_scan3<<<SCB, 256>>>();
  k_prep2<<<(MM + 255)/256, 256>>>(ei, ea, eb2);

  cudaStreamWaitEvent(0, evB, 0);

  const int GRID_AGG = (NN*32 + 255)/256;
  k_agg<<<GRID_AGG, 256>>>(hmA_p);
  k_gruf<<<296, 256, GRUF_SMEM>>>(hA_p, hB_p, hmB_p, bih, bhh, msb);

  k_agg<<<GRID_AGG, 256>>>(hmB_p);
  k_gruf<<<296, 256, GRUF_SMEM>>>(hB_p, hA_p, hmA_p, bih, bhh, msb);

  k_agg<<<GRID_AGG, 256>>>(hmA_p);
  k_gru<<<296, 256, GRU_SMEM>>>(hA_p, hB_p, bih, bhh);

  k_AB<<<1184, 256>>>(hB_p, db1);
  k_dec<<<(MM + 255)/256, 256>>>(ea, out, db2, dW3, db3);
}